// round 8
// baseline (speedup 1.0000x reference)
#include <cuda_runtime.h>
#include <cstdint>

// Problem constants (16 clips of 10 s @ 48 kHz)
#define N_SAMP  480000
#define NP1     480001          // envelope length per row
#define WIN     240             // 5 ms box filter
#define EPSF    1e-6f
#define LN2     0.6931471805599453

// Tiling
#define NTHR    512             // 256 per signal (parallel halves)
#define EPT     16              // d elements per prefix thread
#define T_OUT   3840            // envelope outputs per block
#define L_DV    (T_OUT + WIN - 1)   // 4079 valid d elements per tile
#define PPAD    4352            // padded R array (max idx 4079+254 = 4333)
#define NENV    480             // env threads; 8 outputs each
#define MAXB    16

// Scratch (zero-initialized at load; reset by last block each run)
struct RowAcc { double s1, s2; int m; int pad[3]; };
__device__ RowAcc       g_acc[MAXB];
__device__ unsigned int g_count;

struct SMF {
    float  Rp[PPAD], Rt[PPAD];  // thread-local exclusive partial prefixes
    float  Wp[256],  Wt[256];   // per-thread global bases: P[k]=R[k]+W[k>>4]
    float  wsP[8],   wsT[8];
    float  r1[16], r2[16], r3[16];
    double fin[MAXB];
    int    flag;
};

__device__ __forceinline__ void named_bar(int id) {
    asm volatile("bar.sync %0, %1;" :: "r"(id), "r"(256) : "memory");
}

// Build R (store-early, regs die fast) and return thread total.
// d[m] = |x[id]-x[id-1]|, id = j0-120+m, m in [16*gt, 16*gt+16).
template<bool INTERIOR>
__device__ __forceinline__ float build_R(const float* __restrict__ x, int j0,
                                         int gt, int lane,
                                         float* __restrict__ R)
{
    const int m0 = gt * EPT;
    const int kp = 17 * gt;              // padded base; bank 17*lane, conflict-free
    float s = 0.f;
    if (INTERIOR) {
        float h = 0.f;
        if (lane == 0) h = x[j0 - 121 + m0];
        const float4* p4 = reinterpret_cast<const float4*>(x + (j0 - 120 + m0));
        float4 A0 = p4[0], A1 = p4[1], A2 = p4[2], A3 = p4[3];
        float e[EPT] = { A0.x, A0.y, A0.z, A0.w,  A1.x, A1.y, A1.z, A1.w,
                         A2.x, A2.y, A2.z, A2.w,  A3.x, A3.y, A3.z, A3.w };
        float prev = __shfl_up_sync(0xffffffffu, A3.w, 1);
        if (lane == 0) prev = h;
        #pragma unroll
        for (int c = 0; c < EPT; c++) {
            R[kp + c] = s;               // exclusive local prefix
            s += fabsf(e[c] - prev);
            prev = e[c];
        }
    } else {
        float prev;
        {
            int i = j0 - 121 + m0;
            prev = (i >= 0 && i < N_SAMP) ? x[i] : 0.f;
        }
        #pragma unroll
        for (int c = 0; c < EPT; c++) {
            int i = j0 - 120 + m0 + c;   // x index of current elem == d index
            float cur = (i >= 0 && i < N_SAMP) ? x[i] : 0.f;
            bool ok = (i >= 1) && (i < N_SAMP) && (m0 + c < L_DV);
            R[kp + c] = s;
            s += ok ? fabsf(cur - prev) : 0.f;
            prev = cur;
        }
    }
    return s;
}

__global__ __launch_bounds__(NTHR, 4)
void k_fused(const float* __restrict__ y_pred, const float* __restrict__ y_true,
             float* __restrict__ out, int B, double invcnt)
{
    __shared__ SMF sm;
    const int t = threadIdx.x, lane = t & 31, wid = t >> 5;
    const int grp = t >> 8;             // 0: y_true, 1: y_pred
    const int gt  = t & 255;
    const int gw  = gt >> 5;
    const int row = blockIdx.y;
    const int j0  = blockIdx.x * T_OUT;
    const float* xs = (grp ? y_pred : y_true) + (size_t)row * N_SAMP;
    float* R  = grp ? sm.Rp  : sm.Rt;
    float* W  = grp ? sm.Wp  : sm.Wt;
    float* ws = grp ? sm.wsP : sm.wsT;

    const bool interior = (blockIdx.x >= 1) && (blockIdx.x + 2 < gridDim.x);

    float s = interior ? build_R<true >(xs, j0, gt, lane, R)
                       : build_R<false>(xs, j0, gt, lane, R);

    // Warp inclusive scan of thread totals
    float v = s;
    #pragma unroll
    for (int off = 1; off < 32; off <<= 1) {
        float u = __shfl_up_sync(0xffffffffu, v, off);
        if (lane >= off) v += u;
    }
    if (lane == 31) ws[gw] = v;
    named_bar(1 + grp);                 // group-local; drains STS

    float base = v - s;
    #pragma unroll
    for (int w = 0; w < 7; w++)
        if (w < gw) base += ws[w];
    W[gt] = base;
    __syncthreads();

    // ---- Envelopes + partial sums: 480 threads, strided jj = t + 480c ----
    float s1 = 0.f, s2 = 0.f, mx = 0.f;
    if (t < NENV) {
        const float inv = 1.f / (float)WIN;
        #pragma unroll
        for (int c = 0; c < 8; c++) {
            int jj = t + NENV * c;                 // < 3840
            if (interior || (j0 + jj < NP1)) {
                int ka = jj,        kb = jj + WIN;
                int ta = ka >> 4,   tb = kb >> 4;
                int pa = ka + ta,   pb = kb + tb;  // padded idx, lane-stride 1
                float Ep = (sm.Rp[pb] + sm.Wp[tb] - sm.Rp[pa] - sm.Wp[ta]) * inv;
                float Et = (sm.Rt[pb] + sm.Wt[tb] - sm.Rt[pa] - sm.Wt[ta]) * inv;
                float df = fabsf(__log2f(Ep + EPSF) - __log2f(Et + EPSF));
                s1 += df; s2 += df * Et; mx = fmaxf(mx, Et);
            }
        }
    }

    // ---- Block reduction of (S1, S2, M) over 16 warps ----
    #pragma unroll
    for (int off = 16; off > 0; off >>= 1) {
        s1 += __shfl_down_sync(0xffffffffu, s1, off);
        s2 += __shfl_down_sync(0xffffffffu, s2, off);
        mx  = fmaxf(mx, __shfl_down_sync(0xffffffffu, mx, off));
    }
    if (lane == 0) { sm.r1[wid] = s1; sm.r2[wid] = s2; sm.r3[wid] = mx; }
    __syncthreads();

    if (t == 0) {
        float a1 = 0.f, a2 = 0.f, am = 0.f;
        #pragma unroll
        for (int w = 0; w < 16; w++) {
            a1 += sm.r1[w]; a2 += sm.r2[w]; am = fmaxf(am, sm.r3[w]);
        }
        // values accumulated in log2 domain -> scale by ln2 here
        atomicAdd(&g_acc[row].s1, (double)a1 * LN2);
        atomicAdd(&g_acc[row].s2, (double)a2 * LN2);
        atomicMax(&g_acc[row].m, __float_as_int(am));   // valid: env >= 0
        __threadfence();

        unsigned int total = gridDim.x * gridDim.y;
        unsigned int old = atomicAdd(&g_count, 1u);
        sm.flag = (old == total - 1u) ? 1 : 0;
    }
    __syncthreads();

    if (sm.flag) {
        // Last block: finalize in parallel, reset scratch for next replay.
        __threadfence();
        if (t < B) {
            volatile double* p1 = &g_acc[t].s1;
            volatile double* p2 = &g_acc[t].s2;
            volatile int*    pm = &g_acc[t].m;
            double S1 = *p1;
            double S2 = *p2;
            float  M  = __int_as_float(*pm);
            sm.fin[t] = 0.2 * S1 + 0.8 * S2 / ((double)M + (double)EPSF);
            g_acc[t].s1 = 0.0; g_acc[t].s2 = 0.0; g_acc[t].m = 0;
        }
        __syncthreads();
        if (t == 0) {
            double tot = 0.0;
            for (int r = 0; r < B; r++) tot += sm.fin[r];
            out[0] = (float)(tot * invcnt);
            g_count = 0u;
            __threadfence();
        }
    }
}

extern "C" void kernel_launch(void* const* d_in, const int* in_sizes, int n_in,
                              void* d_out, int out_size)
{
    const float* y_pred = (const float*)d_in[0];
    const float* y_true = (const float*)d_in[1];
    float* out = (float*)d_out;

    const int B     = in_sizes[0] / N_SAMP;              // 16
    const int tiles = (NP1 + T_OUT - 1) / T_OUT;         // 126

    k_fused<<<dim3(tiles, B), NTHR>>>(y_pred, y_true, out, B,
                                      1.0 / ((double)B * (double)NP1));
}

// round 10
// speedup vs baseline: 1.2776x; 1.2776x over previous
#include <cuda_runtime.h>
#include <cstdint>

// Problem constants (16 clips of 10 s @ 48 kHz)
#define N_SAMP  480000
#define NP1     480001          // envelope length per row
#define WIN     240             // 5 ms box filter
#define EPSF    1e-6f
#define EPSW    (240.0f * 1e-6f)   // eps on raw window sums: S/240 + eps = (S+240eps)/240
#define LN2     0.6931471805599453

// Tiling: 256 threads, 16 d-elements each; window offset 240 = 15 thread slots.
#define NTHR    256
#define EPT     16
#define T_OUT   3840            // envelope outputs per block (threads 0..239 x 16)
#define L_DV    (T_OUT + WIN - 1)   // 4079 valid d elements per tile
#define PPAD    4352            // padded P array: idx 17t+c, max 17*255+15 = 4350
#define MAXB    16

// Scratch (zero-initialized at load; reset by last block each run)
struct RowAcc { double s1, s2; int m; int pad[3]; };
__device__ RowAcc       g_acc[MAXB];
__device__ unsigned int g_count;

struct SMF {
    float  Ps[PPAD];            // padded exclusive prefix (reused by both passes)
    float  ws1[8], ws2[8];      // per-pass warp totals
    float  r1[8], r2[8], r3[8];
    double fin[MAXB];
    int    flag;
};

// Thread-local diffs d[m], m in [m0,m0+16), d[m]=|x[id]-x[id-1]|, id=j0-120+m.
template<bool INTERIOR>
__device__ __forceinline__ float diffs(const float* __restrict__ x, int j0,
                                       int m0, int lane, float run[EPT])
{
    if (INTERIOR) {
        float h = 0.f;
        if (lane == 0) h = x[j0 - 121 + m0];       // halo, overlaps vector loads
        const float4* p4 = reinterpret_cast<const float4*>(x + (j0 - 120 + m0));
        float4 A0 = p4[0], A1 = p4[1], A2 = p4[2], A3 = p4[3];
        float e[EPT] = { A0.x, A0.y, A0.z, A0.w,  A1.x, A1.y, A1.z, A1.w,
                         A2.x, A2.y, A2.z, A2.w,  A3.x, A3.y, A3.z, A3.w };
        float prev = __shfl_up_sync(0xffffffffu, A3.w, 1);
        if (lane == 0) prev = h;
        float s = 0.f;
        #pragma unroll
        for (int c = 0; c < EPT; c++) {
            s += fabsf(e[c] - prev);
            prev = e[c];
            run[c] = s;
        }
        return s;
    } else {
        float s = 0.f, prev;
        {
            int i = j0 - 121 + m0;
            prev = (i >= 0 && i < N_SAMP) ? x[i] : 0.f;
        }
        #pragma unroll
        for (int c = 0; c < EPT; c++) {
            int i = j0 - 120 + m0 + c;             // x index == d index
            float cur = (i >= 0 && i < N_SAMP) ? x[i] : 0.f;
            bool ok = (i >= 1) && (i < N_SAMP) && (m0 + c < L_DV);
            s += ok ? fabsf(cur - prev) : 0.f;
            prev = cur;
            run[c] = s;
        }
        return s;
    }
}

// One signal pass: build prefix, then S[c] = P[16(t+15)+c] - P[16t+c]
// (raw window sums = 240*env). Own P from registers, neighbor from smem.
// Contains two __syncthreads; the first also protects Ps reuse across passes.
template<bool INTERIOR>
__device__ __forceinline__ void pass(const float* __restrict__ x, int j0,
                                     int t, int lane, int wid,
                                     float* __restrict__ Ps,
                                     float* __restrict__ ws,
                                     float S[EPT])
{
    float run[EPT];
    float s = diffs<INTERIOR>(x, j0, t * EPT, lane, run);

    float v = s;
    #pragma unroll
    for (int off = 1; off < 32; off <<= 1) {
        float u = __shfl_up_sync(0xffffffffu, v, off);
        if (lane >= off) v += u;
    }
    if (lane == 31) ws[wid] = v;
    __syncthreads();    // ws visible; ALSO guards Ps overwrite vs prior pass reads

    float base = v - s;
    #pragma unroll
    for (int w = 0; w < 7; w++)
        if (w < wid) base += ws[w];

    // P[16t+c] at padded idx 17t+c; bank 17*lane mod 32 -> conflict-free.
    const int kp = 17 * t;
    Ps[kp] = base;
    #pragma unroll
    for (int c = 1; c < EPT; c++) Ps[kp + c] = base + run[c - 1];
    __syncthreads();

    if (t < T_OUT / EPT) {                          // t < 240
        const int kq = kp + 255;                    // padded idx of 16(t+15)
        #pragma unroll
        for (int c = 0; c < EPT; c++) {
            float Pown = base + (c ? run[c - 1] : 0.f);
            S[c] = Ps[kq + c] - Pown;               // lane stride 17: conflict-free
        }
    }
}

__global__ __launch_bounds__(NTHR, 5)
void k_fused(const float* __restrict__ y_pred, const float* __restrict__ y_true,
             float* __restrict__ out, int B, double invcnt)
{
    __shared__ SMF sm;
    const int t = threadIdx.x, lane = t & 31, wid = t >> 5;
    const int row = blockIdx.y;
    const int j0  = blockIdx.x * T_OUT;
    const float* xp = y_pred + (size_t)row * N_SAMP;
    const float* xt = y_true + (size_t)row * N_SAMP;

    const bool interior = (blockIdx.x >= 1) && (blockIdx.x + 2 < gridDim.x);

    float Sp[EPT], St[EPT];
    if (interior) {
        pass<true >(xp, j0, t, lane, wid, sm.Ps, sm.ws1, Sp);
        pass<true >(xt, j0, t, lane, wid, sm.Ps, sm.ws2, St);
    } else {
        pass<false>(xp, j0, t, lane, wid, sm.Ps, sm.ws1, Sp);
        pass<false>(xt, j0, t, lane, wid, sm.Ps, sm.ws2, St);
    }

    // ---- Loss terms on raw window sums (S = 240*env); log2(240) cancels ----
    float s1 = 0.f, s2 = 0.f, mx = 0.f;
    if (t < T_OUT / EPT) {
        #pragma unroll
        for (int c = 0; c < EPT; c++) {
            if (interior || (j0 + t * EPT + c < NP1)) {
                float df = fabsf(__log2f(Sp[c] + EPSW) - __log2f(St[c] + EPSW));
                s1 += df; s2 += df * St[c]; mx = fmaxf(mx, St[c]);
            }
        }
    }

    // ---- Block reduction of (S1, S2, M) ----
    #pragma unroll
    for (int off = 16; off > 0; off >>= 1) {
        s1 += __shfl_down_sync(0xffffffffu, s1, off);
        s2 += __shfl_down_sync(0xffffffffu, s2, off);
        mx  = fmaxf(mx, __shfl_down_sync(0xffffffffu, mx, off));
    }
    if (lane == 0) { sm.r1[wid] = s1; sm.r2[wid] = s2; sm.r3[wid] = mx; }
    __syncthreads();

    if (t == 0) {
        float a1 = 0.f, a2 = 0.f, am = 0.f;
        #pragma unroll
        for (int w = 0; w < 8; w++) {
            a1 += sm.r1[w]; a2 += sm.r2[w]; am = fmaxf(am, sm.r3[w]);
        }
        atomicAdd(&g_acc[row].s1, (double)a1 * LN2);   // log2 -> ln
        atomicAdd(&g_acc[row].s2, (double)a2 * LN2);
        atomicMax(&g_acc[row].m, __float_as_int(am));  // raw window-sum max, >= 0
        __threadfence();

        unsigned int total = gridDim.x * gridDim.y;
        unsigned int old = atomicAdd(&g_count, 1u);
        sm.flag = (old == total - 1u) ? 1 : 0;
    }
    __syncthreads();

    if (sm.flag) {
        // Last block: finalize in parallel, reset scratch for next replay.
        __threadfence();
        if (t < B) {
            volatile double* p1 = &g_acc[t].s1;
            volatile double* p2 = &g_acc[t].s2;
            volatile int*    pm = &g_acc[t].m;
            double S1 = *p1;           // = sum df          (true scale)
            double S2 = *p2;           // = sum df * S_t    (240x true scale)
            float  M  = __int_as_float(*pm);   // = 240 * true max
            // 0.2*S1 + 0.8*(S2/240)/((M/240)+eps) = 0.2*S1 + 0.8*S2/(M+240eps)
            sm.fin[t] = 0.2 * S1 + 0.8 * S2 / ((double)M + (double)EPSW);
            g_acc[t].s1 = 0.0; g_acc[t].s2 = 0.0; g_acc[t].m = 0;
        }
        __syncthreads();
        if (t == 0) {
            double tot = 0.0;
            for (int r = 0; r < B; r++) tot += sm.fin[r];
            out[0] = (float)(tot * invcnt);
            g_count = 0u;
            __threadfence();
        }
    }
}

extern "C" void kernel_launch(void* const* d_in, const int* in_sizes, int n_in,
                              void* d_out, int out_size)
{
    const float* y_pred = (const float*)d_in[0];
    const float* y_true = (const float*)d_in[1];
    float* out = (float*)d_out;

    const int B     = in_sizes[0] / N_SAMP;              // 16
    const int tiles = (NP1 + T_OUT - 1) / T_OUT;         // 126

    k_fused<<<dim3(tiles, B), NTHR>>>(y_pred, y_true, out, B,
                                      1.0 / ((double)B * (double)NP1));
}

// round 11
// speedup vs baseline: 1.2956x; 1.0140x over previous
#include <cuda_runtime.h>
#include <cuda_fp16.h>
#include <cstdint>

// Problem constants (16 clips of 10 s @ 48 kHz)
#define N_SAMP  480000
#define NP1     480001          // envelope length per row
#define WIN     240             // 5 ms box filter
#define EPSF    1e-6f
#define EPSW    (240.0f * 1e-6f)   // eps on raw window sums
#define LN2     0.6931471805599453

// Tiling: 256 threads, 16 d-elements each; window offset 240 = 15 thread slots.
#define NTHR    256
#define EPT     16
#define T_OUT   3840            // envelope outputs per block (threads 0..239 x 16)
#define L_DV    (T_OUT + WIN - 1)   // 4079 valid d elements per tile
#define MAXB    16

// Scratch (zero-initialized at load; reset by last block each run)
struct RowAcc { double s1, s2; int m; int pad[3]; };
__device__ RowAcc       g_acc[MAXB];
__device__ unsigned int g_count;

struct SMF {
    float   base[NTHR];         // per-thread exclusive prefix base (fp32)
    __half2 run2[NTHR * 9];     // per-thread local prefix, half2-packed, idx 9t+k
    float   ws1[8], ws2[8];
    float   r1[8], r2[8], r3[8];
    double  fin[MAXB];
    int     flag;
};

// Thread-local diffs d[m], m in [m0,m0+16), d[m]=|x[id]-x[id-1]|, id=j0-120+m.
template<bool INTERIOR>
__device__ __forceinline__ float diffs(const float* __restrict__ x, int j0,
                                       int m0, int lane, float run[EPT])
{
    if (INTERIOR) {
        float h = 0.f;
        if (lane == 0) h = x[j0 - 121 + m0];       // halo, overlaps vector loads
        const float4* p4 = reinterpret_cast<const float4*>(x + (j0 - 120 + m0));
        float4 A0 = p4[0], A1 = p4[1], A2 = p4[2], A3 = p4[3];
        float e[EPT] = { A0.x, A0.y, A0.z, A0.w,  A1.x, A1.y, A1.z, A1.w,
                         A2.x, A2.y, A2.z, A2.w,  A3.x, A3.y, A3.z, A3.w };
        float prev = __shfl_up_sync(0xffffffffu, A3.w, 1);
        if (lane == 0) prev = h;
        float s = 0.f;
        #pragma unroll
        for (int c = 0; c < EPT; c++) {
            s += fabsf(e[c] - prev);
            prev = e[c];
            run[c] = s;
        }
        return s;
    } else {
        float s = 0.f, prev;
        {
            int i = j0 - 121 + m0;
            prev = (i >= 0 && i < N_SAMP) ? x[i] : 0.f;
        }
        #pragma unroll
        for (int c = 0; c < EPT; c++) {
            int i = j0 - 120 + m0 + c;             // x index == d index
            float cur = (i >= 0 && i < N_SAMP) ? x[i] : 0.f;
            bool ok = (i >= 1) && (i < N_SAMP) && (m0 + c < L_DV);
            s += ok ? fabsf(cur - prev) : 0.f;
            prev = cur;
            run[c] = s;
        }
        return s;
    }
}

// One signal pass: S[c] = P[16(t+15)+c] - P[16t+c]  (raw window sums = 240*env).
// Own P from fp32 registers; neighbor P = base[t+15] (fp32 smem) + run (half2 smem).
template<bool INTERIOR>
__device__ __forceinline__ void pass(const float* __restrict__ x, int j0,
                                     int t, int lane, int wid,
                                     SMF& sm, float* __restrict__ ws,
                                     float S[EPT])
{
    float run[EPT];
    float s = diffs<INTERIOR>(x, j0, t * EPT, lane, run);

    float v = s;
    #pragma unroll
    for (int off = 1; off < 32; off <<= 1) {
        float u = __shfl_up_sync(0xffffffffu, v, off);
        if (lane >= off) v += u;
    }
    if (lane == 31) ws[wid] = v;
    __syncthreads();    // ws visible; ALSO guards smem overwrite vs prior pass reads

    float base = v - s;
    #pragma unroll
    for (int w = 0; w < 7; w++)
        if (w < wid) base += ws[w];

    // Write base (lane stride 1) + packed run (idx 9t+k, lane stride 9: CF)
    sm.base[t] = base;
    __half2* rp = &sm.run2[9 * t];
    #pragma unroll
    for (int k = 0; k < 8; k++)
        rp[k] = __floats2half2_rn(run[2 * k], run[2 * k + 1]);
    __syncthreads();

    if (t < T_OUT / EPT) {                          // t < 240
        float baseN = sm.base[t + 15];
        const __half2* rq = &sm.run2[9 * (t + 15)];
        float rn[EPT];
        #pragma unroll
        for (int k = 0; k < 8; k++) {
            float2 f = __half22float2(rq[k]);       // lane stride 9: conflict-free
            rn[2 * k] = f.x; rn[2 * k + 1] = f.y;
        }
        S[0] = baseN - base;
        #pragma unroll
        for (int c = 1; c < EPT; c++)
            S[c] = (baseN + rn[c - 1]) - (base + run[c - 1]);
    }
}

__global__ __launch_bounds__(NTHR, 5)
void k_fused(const float* __restrict__ y_pred, const float* __restrict__ y_true,
             float* __restrict__ out, int B, double invcnt)
{
    __shared__ SMF sm;
    const int t = threadIdx.x, lane = t & 31, wid = t >> 5;
    const int row = blockIdx.y;
    const int j0  = blockIdx.x * T_OUT;
    const float* xp = y_pred + (size_t)row * N_SAMP;
    const float* xt = y_true + (size_t)row * N_SAMP;

    const bool interior = (blockIdx.x >= 1) && (blockIdx.x + 2 < gridDim.x);

    float Sp[EPT], St[EPT];
    if (interior) {
        pass<true >(xp, j0, t, lane, wid, sm, sm.ws1, Sp);
        pass<true >(xt, j0, t, lane, wid, sm, sm.ws2, St);
    } else {
        pass<false>(xp, j0, t, lane, wid, sm, sm.ws1, Sp);
        pass<false>(xt, j0, t, lane, wid, sm, sm.ws2, St);
    }

    // ---- Loss terms on raw window sums (S = 240*env); log2(240) cancels ----
    float s1 = 0.f, s2 = 0.f, mx = 0.f;
    if (t < T_OUT / EPT) {
        #pragma unroll
        for (int c = 0; c < EPT; c++) {
            if (interior || (j0 + t * EPT + c < NP1)) {
                float df = fabsf(__log2f(Sp[c] + EPSW) - __log2f(St[c] + EPSW));
                s1 += df; s2 += df * St[c]; mx = fmaxf(mx, St[c]);
            }
        }
    }

    // ---- Block reduction of (S1, S2, M) ----
    #pragma unroll
    for (int off = 16; off > 0; off >>= 1) {
        s1 += __shfl_down_sync(0xffffffffu, s1, off);
        s2 += __shfl_down_sync(0xffffffffu, s2, off);
        mx  = fmaxf(mx, __shfl_down_sync(0xffffffffu, mx, off));
    }
    if (lane == 0) { sm.r1[wid] = s1; sm.r2[wid] = s2; sm.r3[wid] = mx; }
    __syncthreads();

    if (t == 0) {
        float a1 = 0.f, a2 = 0.f, am = 0.f;
        #pragma unroll
        for (int w = 0; w < 8; w++) {
            a1 += sm.r1[w]; a2 += sm.r2[w]; am = fmaxf(am, sm.r3[w]);
        }
        atomicAdd(&g_acc[row].s1, (double)a1 * LN2);   // log2 -> ln
        atomicAdd(&g_acc[row].s2, (double)a2 * LN2);
        atomicMax(&g_acc[row].m, __float_as_int(am));  // raw window-sum max, >= 0
        __threadfence();

        unsigned int total = gridDim.x * gridDim.y;
        unsigned int old = atomicAdd(&g_count, 1u);
        sm.flag = (old == total - 1u) ? 1 : 0;
    }
    __syncthreads();

    if (sm.flag) {
        // Last block: finalize in parallel, reset scratch for next replay.
        __threadfence();
        if (t < B) {
            volatile double* p1 = &g_acc[t].s1;
            volatile double* p2 = &g_acc[t].s2;
            volatile int*    pm = &g_acc[t].m;
            double S1 = *p1;                   // sum df            (true scale)
            double S2 = *p2;                   // sum df * S_t      (240x scale)
            float  M  = __int_as_float(*pm);   // 240 * true max
            sm.fin[t] = 0.2 * S1 + 0.8 * S2 / ((double)M + (double)EPSW);
            g_acc[t].s1 = 0.0; g_acc[t].s2 = 0.0; g_acc[t].m = 0;
        }
        __syncthreads();
        if (t == 0) {
            double tot = 0.0;
            for (int r = 0; r < B; r++) tot += sm.fin[r];
            out[0] = (float)(tot * invcnt);
            g_count = 0u;
            __threadfence();
        }
    }
}

extern "C" void kernel_launch(void* const* d_in, const int* in_sizes, int n_in,
                              void* d_out, int out_size)
{
    const float* y_pred = (const float*)d_in[0];
    const float* y_true = (const float*)d_in[1];
    float* out = (float*)d_out;

    const int B     = in_sizes[0] / N_SAMP;              // 16
    const int tiles = (NP1 + T_OUT - 1) / T_OUT;         // 126

    k_fused<<<dim3(tiles, B), NTHR>>>(y_pred, y_true, out, B,
                                      1.0 / ((double)B * (double)NP1));
}